// round 1
// baseline (speedup 1.0000x reference)
#include <cuda_runtime.h>

#define ALPHA_C 1.702f
#define LIMIT_C 7.0f

// Scratch for the activated intermediate: 8 experts x 1024 x 2048 fp32 = 64 MB.
// __device__ global (allocation rules forbid cudaMalloc).
static __device__ float g_act[8ull * 1024ull * 2048ull];

// Classic 128x128x8 SGEMM, 256 threads, 8x8 per-thread register tile.
// FUSE_ACT=true : C = activation(A@B + bias) pair-interleaved (gate=even col, up=odd col),
//                 writes to g_act (N/2 output columns).
// FUSE_ACT=false: C = A@B + bias, A read from g_act, writes to Call (the final output).
template <bool FUSE_ACT>
__global__ __launch_bounds__(256, 2)
void moe_sgemm(const float* __restrict__ Aall,
               const float* __restrict__ Ball,
               const float* __restrict__ biasAll,
               float* __restrict__ Call,
               int M, int N, int K,
               size_t sA, size_t sB, size_t sBias, size_t sC)
{
    constexpr int BM = 128, BN = 128, BK = 8, TM = 8, TN = 8;
    __shared__ float As[BK][BM];   // A tile stored transposed: As[k][m]
    __shared__ float Bs[BK][BN];

    const int e = blockIdx.z;
    const float* A = FUSE_ACT ? (Aall + (size_t)e * sA)
                              : (g_act + (size_t)e * sA);
    const float* B = Ball + (size_t)e * sB;
    const float* bias = biasAll + (size_t)e * sBias;
    float* C = FUSE_ACT ? (g_act + (size_t)e * sC)
                        : (Call + (size_t)e * sC);

    const int rowB = blockIdx.y * BM;
    const int colB = blockIdx.x * BN;
    const int tid = threadIdx.x;

    // A tile load: 128 rows x 8 k -> 1024 floats; one float4 per thread.
    const int aRow = tid >> 1;
    const int aK   = (tid & 1) * 4;
    // B tile load: 8 k x 128 cols -> 1024 floats; one float4 per thread.
    const int bK   = tid >> 5;
    const int bCol = (tid & 31) * 4;

    // Compute mapping: 16x16 thread grid of 8x8 micro tiles.
    const int ty = tid >> 4;   // 0..15 -> rows
    const int tx = tid & 15;   // 0..15 -> cols

    float acc[TM][TN];
#pragma unroll
    for (int i = 0; i < TM; i++)
#pragma unroll
        for (int j = 0; j < TN; j++) acc[i][j] = 0.f;

    const float* aPtr = A + (size_t)(rowB + aRow) * K + aK;
    const float* bPtr = B + (size_t)bK * N + colB + bCol;

    for (int k0 = 0; k0 < K; k0 += BK) {
        float4 av = *(const float4*)(aPtr + k0);
        As[aK + 0][aRow] = av.x;
        As[aK + 1][aRow] = av.y;
        As[aK + 2][aRow] = av.z;
        As[aK + 3][aRow] = av.w;
        float4 bv = *(const float4*)(bPtr + (size_t)k0 * N);
        *(float4*)&Bs[bK][bCol] = bv;
        __syncthreads();

#pragma unroll
        for (int k = 0; k < BK; k++) {
            float4 a0 = *(const float4*)&As[k][ty * TM];
            float4 a1 = *(const float4*)&As[k][ty * TM + 4];
            float4 b0 = *(const float4*)&Bs[k][tx * TN];
            float4 b1 = *(const float4*)&Bs[k][tx * TN + 4];
            float ra[TM] = {a0.x, a0.y, a0.z, a0.w, a1.x, a1.y, a1.z, a1.w};
            float rb[TN] = {b0.x, b0.y, b0.z, b0.w, b1.x, b1.y, b1.z, b1.w};
#pragma unroll
            for (int i = 0; i < TM; i++)
#pragma unroll
                for (int j = 0; j < TN; j++)
                    acc[i][j] = fmaf(ra[i], rb[j], acc[i][j]);
        }
        __syncthreads();
    }

    if (FUSE_ACT) {
        // gu columns: even = gate, odd = up. act col = gucol/2. N here = 4096.
        const int halfN = N >> 1;
#pragma unroll
        for (int i = 0; i < TM; i++) {
            const int m = rowB + ty * TM + i;
#pragma unroll
            for (int p = 0; p < 4; p++) {
                const int gucol = colB + tx * TN + 2 * p;   // even
                float g = acc[i][2 * p]     + bias[gucol];
                float u = acc[i][2 * p + 1] + bias[gucol + 1];
                g = fminf(g, LIMIT_C);
                u = fminf(fmaxf(u, -LIMIT_C), LIMIT_C);
                // g * sigmoid(ALPHA*g)
                float glu = g / (1.f + __expf(-ALPHA_C * g));
                C[(size_t)m * halfN + (gucol >> 1)] = (u + 1.f) * glu;
            }
        }
    } else {
#pragma unroll
        for (int i = 0; i < TM; i++) {
            const int m = rowB + ty * TM + i;
#pragma unroll
            for (int j = 0; j < TN; j += 4) {
                const int col = colB + tx * TN + j;
                float4 v;
                v.x = acc[i][j + 0] + bias[col + 0];
                v.y = acc[i][j + 1] + bias[col + 1];
                v.z = acc[i][j + 2] + bias[col + 2];
                v.w = acc[i][j + 3] + bias[col + 3];
                *(float4*)&C[(size_t)m * N + col] = v;
            }
        }
    }
}

extern "C" void kernel_launch(void* const* d_in, const int* in_sizes, int n_in,
                              void* d_out, int out_size)
{
    // metadata order: dispatched, w1, w1_bias, w2, w2_bias, sparsity_remap, BD, S
    const float* disp = (const float*)d_in[0];  // (1,1,8,1024,2048)
    const float* w1   = (const float*)d_in[1];  // (8,2048,4096)
    const float* b1   = (const float*)d_in[2];  // (8,4096)
    const float* w2   = (const float*)d_in[3];  // (8,2048,2048)
    const float* b2   = (const float*)d_in[4];  // (8,2048)
    // sparsity_remap / BD / S unused by the reference math.
    float* out = (float*)d_out;                 // (8,1,1024,2048) fp32

    const int E = 8, M = 1024, H = 2048, I2 = 4096, I = 2048;

    dim3 blk(256);

    // Kernel 1: gu = disp @ w1 + b1, fused clipped-GLU activation -> g_act
    dim3 g1(I2 / 128, M / 128, E);
    moe_sgemm<true><<<g1, blk>>>(disp, w1, b1, /*Call unused*/ nullptr,
                                 M, I2, H,
                                 (size_t)M * H, (size_t)H * I2,
                                 (size_t)I2, (size_t)M * I);

    // Kernel 2: out = g_act @ w2 + b2
    dim3 g2(H / 128, M / 128, E);
    moe_sgemm<false><<<g2, blk>>>(/*Aall unused*/ nullptr, w2, b2, out,
                                  M, H, I,
                                  (size_t)M * I, (size_t)I * H,
                                  (size_t)H, (size_t)M * H);
}

// round 3
// speedup vs baseline: 3.6450x; 3.6450x over previous
#include <cuda_runtime.h>
#include <cstdint>

// Scratch: activated intermediate, 8 x 1024 x 2048 fp32 = 64 MB.
static __device__ float g_act[8ull * 1024 * 2048];

// ---------------- PTX helpers ----------------
__device__ __forceinline__ uint32_t s2u(const void* p) {
    uint32_t a;
    asm("{ .reg .u64 t; cvta.to.shared.u64 t, %1; cvt.u32.u64 %0, t; }" : "=r"(a) : "l"(p));
    return a;
}
__device__ __forceinline__ uint32_t tf32cvt(float x) {
    uint32_t r; asm("cvt.rna.tf32.f32 %0, %1;" : "=r"(r) : "f"(x)); return r;
}
#define CP_ASYNC16(dst, src) \
    asm volatile("cp.async.cg.shared.global [%0], [%1], 16;" :: "r"(dst), "l"(src))
#define CP_COMMIT() asm volatile("cp.async.commit_group;")
#define CP_WAIT(n)  asm volatile("cp.async.wait_group %0;" :: "n"(n))

__device__ __forceinline__ void mma_tf32(float c[4], uint32_t a0, uint32_t a1, uint32_t a2,
                                         uint32_t a3, uint32_t b0, uint32_t b1) {
    asm("mma.sync.aligned.m16n8k8.row.col.f32.tf32.tf32.f32 "
        "{%0,%1,%2,%3}, {%4,%5,%6,%7}, {%8,%9}, {%0,%1,%2,%3};"
        : "+f"(c[0]), "+f"(c[1]), "+f"(c[2]), "+f"(c[3])
        : "r"(a0), "r"(a1), "r"(a2), "r"(a3), "r"(b0), "r"(b1));
}

// ---------------- main GEMM ----------------
// C[128,128] per CTA, 8 warps as 2(M) x 4(N) of 64x32 warp tiles, BK=32, 3-stage cp.async.
// EPI 0: gu = A@B + bias -> clipped GLU -> g_act (N=4096, halved cols).
// EPI 1: out = A@B + bias.
template <int EPI>
__global__ void __launch_bounds__(256)
moe_mma_sync(const float* __restrict__ Aall,
             const float* __restrict__ Ball,
             const float* __restrict__ biasAll,
             float* __restrict__ outAll,
             int M, int N, int K)
{
    constexpr int BM = 128, BN = 128, BK = 32, STG = 3;
    constexpr int AST = 36;    // A smem row stride (floats): 36 mod 32 = 4 -> conflict-free frags
    constexpr int BST = 136;   // B smem row stride (floats): 136 mod 32 = 8 -> conflict-free frags
    constexpr int A_ST = BM * AST;   // floats per A stage
    constexpr int B_ST = BK * BST;   // floats per B stage

    extern __shared__ float smem[];
    float* As = smem;
    float* Bs = smem + STG * A_ST;
    const uint32_t as_u = s2u(As);
    const uint32_t bs_u = s2u(Bs);

    const int tid  = threadIdx.x;
    const int lane = tid & 31;
    const int warp = tid >> 5;
    const int wm = warp & 1;        // 0..1  (M)
    const int wn = warp >> 1;       // 0..3  (N)
    const int r = lane >> 2;        // 0..7
    const int c = lane & 3;         // 0..3

    const int e  = blockIdx.z;
    const int mB = blockIdx.y * BM;
    const int nB = blockIdx.x * BN;

    const float* A = Aall + (size_t)e * M * K;
    const float* B = Ball + (size_t)e * K * N;
    const float* bias = biasAll + (size_t)e * N;

    const float* Asrc0 = A + (size_t)mB * K;
    const float* Bsrc0 = B + nB;

    // per-thread load coords (4 x 16B chunks per tile each for A and B)
    const int KIT = K / BK;

    auto load_stage = [&](int s, int kt) {
        const float* Asrc = Asrc0 + kt * BK;
        const float* Bsrc = Bsrc0 + (size_t)(kt * BK) * N;
        const uint32_t a_b = as_u + (uint32_t)s * A_ST * 4;
        const uint32_t b_b = bs_u + (uint32_t)s * B_ST * 4;
#pragma unroll
        for (int i = 0; i < 4; i++) {
            int idx = tid + i * 256;
            int ar = idx >> 3, ac = idx & 7;          // A: 128 rows x 8 chunks
            CP_ASYNC16(a_b + (uint32_t)(ar * AST + ac * 4) * 4, Asrc + (size_t)ar * K + ac * 4);
            int br = idx >> 5, bc = idx & 31;         // B: 32 rows x 32 chunks
            CP_ASYNC16(b_b + (uint32_t)(br * BST + bc * 4) * 4, Bsrc + (size_t)br * N + bc * 4);
        }
    };

    float acc[4][4][4];
#pragma unroll
    for (int mi = 0; mi < 4; mi++)
#pragma unroll
        for (int ni = 0; ni < 4; ni++)
#pragma unroll
            for (int q = 0; q < 4; q++) acc[mi][ni][q] = 0.f;

    // prologue: fill STG-1 stages
#pragma unroll
    for (int s = 0; s < STG - 1; s++) { load_stage(s, s); CP_COMMIT(); }

    for (int kt = 0; kt < KIT; kt++) {
        CP_WAIT(STG - 2);
        __syncthreads();
        // prefetch next stage (after sync: target stage's previous compute is done)
        if (kt + STG - 1 < KIT) load_stage((kt + STG - 1) % STG, kt + STG - 1);
        CP_COMMIT();

        const float* Ab = As + (kt % STG) * A_ST;
        const float* Bb = Bs + (kt % STG) * B_ST;
#pragma unroll
        for (int ks = 0; ks < BK / 8; ks++) {
            uint32_t af[4][4];
#pragma unroll
            for (int mi = 0; mi < 4; mi++) {
                int row = wm * 64 + mi * 16 + r;
                int k = ks * 8 + c;
                af[mi][0] = tf32cvt(Ab[row * AST + k]);
                af[mi][1] = tf32cvt(Ab[(row + 8) * AST + k]);
                af[mi][2] = tf32cvt(Ab[row * AST + k + 4]);
                af[mi][3] = tf32cvt(Ab[(row + 8) * AST + k + 4]);
            }
            uint32_t bf[4][2];
#pragma unroll
            for (int ni = 0; ni < 4; ni++) {
                int col = wn * 32 + ni * 8 + r;
                bf[ni][0] = tf32cvt(Bb[(ks * 8 + c) * BST + col]);
                bf[ni][1] = tf32cvt(Bb[(ks * 8 + 4 + c) * BST + col]);
            }
#pragma unroll
            for (int mi = 0; mi < 4; mi++)
#pragma unroll
                for (int ni = 0; ni < 4; ni++)
                    mma_tf32(acc[mi][ni], af[mi][0], af[mi][1], af[mi][2], af[mi][3],
                             bf[ni][0], bf[ni][1]);
        }
    }

    // ---------------- epilogue ----------------
    if (EPI == 0) {
        const int halfN = N >> 1;   // 2048
        float* act = g_act + (size_t)e * M * halfN;
#pragma unroll
        for (int mi = 0; mi < 4; mi++) {
            const int m = mB + wm * 64 + mi * 16 + r;
#pragma unroll
            for (int ni = 0; ni < 4; ni++) {
                const int gucol = nB + wn * 32 + ni * 8 + 2 * c;
                const float bg = __ldg(&bias[gucol]);
                const float bu = __ldg(&bias[gucol + 1]);
#pragma unroll
                for (int h = 0; h < 2; h++) {   // h=0 -> row m, h=1 -> row m+8
                    float g = acc[mi][ni][2 * h]     + bg;
                    float u = acc[mi][ni][2 * h + 1] + bu;
                    g = fminf(g, 7.0f);
                    u = fminf(fmaxf(u, -7.0f), 7.0f);
                    float glu = g / (1.0f + __expf(-1.702f * g));
                    act[(size_t)(m + 8 * h) * halfN + (gucol >> 1)] = (u + 1.0f) * glu;
                }
            }
        }
    } else {
        float* out = outAll + (size_t)e * M * N;
#pragma unroll
        for (int mi = 0; mi < 4; mi++) {
            const int m = mB + wm * 64 + mi * 16 + r;
#pragma unroll
            for (int ni = 0; ni < 4; ni++) {
                const int col = nB + wn * 32 + ni * 8 + 2 * c;
                const float b0 = __ldg(&bias[col]);
                const float b1 = __ldg(&bias[col + 1]);
                float2 v0 = make_float2(acc[mi][ni][0] + b0, acc[mi][ni][1] + b1);
                float2 v1 = make_float2(acc[mi][ni][2] + b0, acc[mi][ni][3] + b1);
                *(float2*)&out[(size_t)m * N + col]       = v0;
                *(float2*)&out[(size_t)(m + 8) * N + col] = v1;
            }
        }
    }
}

// ---------------- host ----------------
extern "C" void kernel_launch(void* const* d_in, const int* in_sizes, int n_in,
                              void* d_out, int out_size)
{
    const float* disp = (const float*)d_in[0];  // (1,1,8,1024,2048)
    const float* w1   = (const float*)d_in[1];  // (8,2048,4096)
    const float* b1   = (const float*)d_in[2];  // (8,4096)
    const float* w2   = (const float*)d_in[3];  // (8,2048,2048)
    const float* b2   = (const float*)d_in[4];  // (8,2048)
    float* out = (float*)d_out;                 // (8,1,1024,2048) fp32

    const int M = 1024, H = 2048, I2 = 4096, I = 2048;

    void* p_act;
    cudaGetSymbolAddress(&p_act, g_act);

    constexpr int STG = 3;
    const int smem_bytes = STG * (128 * 36 + 32 * 136) * 4;   // 107,520 B
    cudaFuncSetAttribute(moe_mma_sync<0>, cudaFuncAttributeMaxDynamicSharedMemorySize, smem_bytes);
    cudaFuncSetAttribute(moe_mma_sync<1>, cudaFuncAttributeMaxDynamicSharedMemorySize, smem_bytes);

    // GEMM1: gu = disp @ w1 (+b1) -> GLU -> g_act
    moe_mma_sync<0><<<dim3(I2 / 128, M / 128, 8), 256, smem_bytes>>>(
        disp, w1, b1, nullptr, M, I2, H);
    // GEMM2: out = g_act @ w2 (+b2)
    moe_mma_sync<1><<<dim3(H / 128, M / 128, 8), 256, smem_bytes>>>(
        (const float*)p_act, w2, b2, out, M, H, I);
}